// round 13
// baseline (speedup 1.0000x reference)
#include <cuda_runtime.h>
#include <cuda_bf16.h>
#include <cstdint>
#include <stdint.h>
#include <math.h>

namespace {
constexpr int kB  = 2;
constexpr int kS  = 1024;
constexpr int kD  = 512;
constexpr int kV  = 32000;
constexpr int kD2 = 2 * kD;   // 1024
constexpr int kD3 = 3 * kD;   // 1536
constexpr int kBS = kB * kS;  // 2048
}

// ---------------- fp32 scratch ----------------
__device__ float g_gx[kBS * kD3];
__device__ float g_sc[kBS * kS];
__device__ float g_h[2][kB * kD];
__device__ int   g_flags[kS * 64];
__device__ float g_gate[kBS];

// ---------------- bf16 scratch ----------------
__device__ __nv_bfloat16 bf_attn[kBS * kD2];
__device__ __nv_bfloat16 bf_Wih[kD3 * kD];
__device__ __nv_bfloat16 bf_Wq[kD2 * kD2];
__device__ __nv_bfloat16 bf_Wk[kD2 * kD2];
__device__ __nv_bfloat16 bf_Wqp[kD * kD2];
__device__ __nv_bfloat16 bf_Wgen[(size_t)kV * kD3];
__device__ __nv_bfloat16 bf_pos[kS * kD];
__device__ __nv_bfloat16 bf_Q[kBS * kD2];
__device__ __nv_bfloat16 bf_K[kBS * kD2];
__device__ __nv_bfloat16 bf_Qp[kBS * kD];
__device__ __nv_bfloat16 bf_probs[kBS * kS];
__device__ __nv_bfloat16 bf_attnT[kB * kD2 * kS];
__device__ __nv_bfloat16 bf_comb[kBS * kD3];

// ================= PTX helpers =================
__device__ __forceinline__ uint32_t smem_u32(const void* p) {
    uint32_t a;
    asm("{ .reg .u64 t; cvta.to.shared.u64 t, %1; cvt.u32.u64 %0, t; }" : "=r"(a) : "l"(p));
    return a;
}
__device__ __forceinline__ void cp16(uint32_t saddr, const void* gaddr) {
    asm volatile("cp.async.cg.shared.global [%0], [%1], 16;" :: "r"(saddr), "l"(gaddr));
}
#define CP_COMMIT() asm volatile("cp.async.commit_group;" ::: "memory")
#define CP_WAIT2()  asm volatile("cp.async.wait_group 2;" ::: "memory")

__device__ __forceinline__ void ldmat_x4(uint32_t& r0, uint32_t& r1, uint32_t& r2, uint32_t& r3,
                                         uint32_t addr) {
    asm volatile("ldmatrix.sync.aligned.m8n8.x4.shared.b16 {%0,%1,%2,%3}, [%4];"
                 : "=r"(r0), "=r"(r1), "=r"(r2), "=r"(r3) : "r"(addr));
}
__device__ __forceinline__ void mma_16816f(float* c, const uint32_t* a, const uint32_t* b) {
    asm volatile("mma.sync.aligned.m16n8k16.row.col.f32.bf16.bf16.f32 "
                 "{%0,%1,%2,%3}, {%4,%5,%6,%7}, {%8,%9}, {%0,%1,%2,%3};"
                 : "+f"(c[0]), "+f"(c[1]), "+f"(c[2]), "+f"(c[3])
                 : "r"(a[0]), "r"(a[1]), "r"(a[2]), "r"(a[3]), "r"(b[0]), "r"(b[1]));
}

// Fast exp on the FMA/ALU pipes (no MUFU). Rel err ~4e-5 for x <= 0.
__device__ __forceinline__ float fexp(float x) {
    x = fmaxf(x, -80.f);
    float y = x * 1.44269504088896f;      // log2(e)
    float t = y + 12582912.f;              // 2^23 * 1.5 magic: round-to-nearest
    float n = t - 12582912.f;
    float f = y - n;
    float p = 9.61597636e-3f;              // Taylor of 2^f: ln2^k/k!
    p = fmaf(p, f, 5.55036329e-2f);
    p = fmaf(p, f, 2.40226507e-1f);
    p = fmaf(p, f, 6.93147182e-1f);
    p = fmaf(p, f, 1.0f);
    int e = __float_as_int(t) << 23;       // n << 23 (magic high bits shift out)
    return __int_as_float(__float_as_int(p) + e);
}

// ================= bf16 HMMA GEMM, cp.async 4-stage (R10 geometry) =================
// 256 threads = 8 warps (2x4), warp tile 64x32. CTA tile 128x128, K-chunk 32, 4 stages.
namespace {
constexpr int TS = 40;
constexpr uint32_t STAGE_BYTES = 256u * TS * 2;         // 20480
constexpr uint32_t TG_SMEM = 4 * STAGE_BYTES;           // 81920
constexpr float kRopeC = 0.017988946039015983f;         // ln(10000)/512
}

template <bool ACC, bool BIAS, bool CAUSAL, bool OUTBF, bool ROPE>
__global__ void __launch_bounds__(256)
tgemm_k(const __nv_bfloat16* __restrict__ A, const __nv_bfloat16* __restrict__ B,
        const float* __restrict__ bias, void* __restrict__ Cv,
        int K, int lda, int ldb, int ldc,
        long long sA, long long sB, long long sC) {
    const int m0 = blockIdx.y << 7;
    const int n0 = blockIdx.x << 7;
    if (CAUSAL && n0 > m0 + 127) return;
    A += (long long)blockIdx.z * sA;
    B += (long long)blockIdx.z * sB;

    extern __shared__ __nv_bfloat16 smem_bf[];
    const uint32_t sbase = smem_u32(smem_bf);

    const int t    = threadIdx.x;
    const int wid  = t >> 5;
    const int lane = t & 31;
    const int wm   = (wid >> 2) << 6;
    const int wn   = (wid & 3) << 5;

    const int rt = t >> 1;
    const int hf = (t & 1) << 4;

    const int a_r   = lane & 15;
    const int a_k   = (lane >> 4) << 3;
    const int b_row = (lane & 7) + ((lane >> 4) << 3);
    const int b_k   = ((lane >> 3) & 1) << 3;

    float acc[4][4][4];
#pragma unroll
    for (int i = 0; i < 4; i++)
#pragma unroll
        for (int j = 0; j < 4; j++)
#pragma unroll
            for (int r = 0; r < 4; r++) acc[i][j][r] = 0.f;

    auto stage_load = [&](int stage, int kb) {
        const __nv_bfloat16* ga = A + (size_t)(m0 + rt) * lda + (kb << 5) + hf;
        uint32_t sa = sbase + stage * STAGE_BYTES + ((uint32_t)(rt * TS + hf) << 1);
        cp16(sa, ga); cp16(sa + 16, ga + 8);
        const __nv_bfloat16* gb = B + (size_t)(n0 + rt) * ldb + (kb << 5) + hf;
        uint32_t sb = sbase + stage * STAGE_BYTES + ((uint32_t)((128 + rt) * TS + hf) << 1);
        cp16(sb, gb); cp16(sb + 16, gb + 8);
    };

    const int NKB = K >> 5;
    stage_load(0, 0);
    CP_COMMIT();
    if (NKB > 1) stage_load(1, 1);
    CP_COMMIT();
    if (NKB > 2) stage_load(2, 2);
    CP_COMMIT();

    int buf = 0;
    for (int kb = 0; kb < NKB; kb++) {
        CP_WAIT2();
        __syncthreads();

        const uint32_t ab = sbase + buf * STAGE_BYTES;
        const uint32_t bb = ab + 128u * TS * 2;
#pragma unroll
        for (int ks = 0; ks < 32; ks += 16) {
            uint32_t af[4][4], bfr[4][2];
#pragma unroll
            for (int mi = 0; mi < 4; mi++) {
                uint32_t addr = ab + ((uint32_t)((wm + (mi << 4) + a_r) * TS + ks + a_k) << 1);
                ldmat_x4(af[mi][0], af[mi][1], af[mi][2], af[mi][3], addr);
            }
#pragma unroll
            for (int np = 0; np < 2; np++) {
                uint32_t addr = bb + ((uint32_t)((wn + (np << 4) + b_row) * TS + ks + b_k) << 1);
                ldmat_x4(bfr[np * 2][0], bfr[np * 2][1],
                         bfr[np * 2 + 1][0], bfr[np * 2 + 1][1], addr);
            }
#pragma unroll
            for (int mi = 0; mi < 4; mi++)
#pragma unroll
                for (int ni = 0; ni < 4; ni++)
                    mma_16816f(acc[mi][ni], af[mi], bfr[ni]);
        }
        if (kb + 3 < NKB) {
            int ns = buf + 3; if (ns >= 4) ns -= 4;
            stage_load(ns, kb + 3);
        }
        CP_COMMIT();
        if (++buf == 4) buf = 0;
    }

    // epilogue
    const int er = lane >> 2;
    const int ec = (lane & 3) << 1;
    if (OUTBF) {
        __nv_bfloat16* Cb = (__nv_bfloat16*)Cv + (long long)blockIdx.z * sC;
#pragma unroll
        for (int mi = 0; mi < 4; mi++) {
#pragma unroll
            for (int rr = 0; rr < 2; rr++) {
                int m = m0 + wm + (mi << 4) + er + (rr << 3);
                __nv_bfloat16* cp = Cb + (size_t)m * ldc + n0 + wn + ec;
                float sp = ROPE ? (float)(m & (kS - 1)) : 0.f;
#pragma unroll
                for (int ni = 0; ni < 4; ni++) {
                    float vx = acc[mi][ni][rr * 2 + 0];
                    float vy = acc[mi][ni][rr * 2 + 1];
                    if (ROPE) {
                        int col = n0 + wn + (ni << 3) + ec;
                        float inv = expf(-kRopeC * (float)(col >> 1));
                        float sn, cs;
                        sincosf(sp * inv, &sn, &cs);
                        float rx = vx * cs - vy * sn;
                        float ry = vy * cs + vx * sn;
                        vx = rx; vy = ry;
                    }
                    __nv_bfloat162 h = __floats2bfloat162_rn(vx, vy);
                    *reinterpret_cast<__nv_bfloat162*>(cp + (ni << 3)) = h;
                }
            }
        }
    } else {
        float* Cf = (float*)Cv + (long long)blockIdx.z * sC;
#pragma unroll
        for (int mi = 0; mi < 4; mi++) {
#pragma unroll
            for (int rr = 0; rr < 2; rr++) {
                int m = m0 + wm + (mi << 4) + er + (rr << 3);
                float* cp = Cf + (size_t)m * ldc + n0 + wn + ec;
#pragma unroll
                for (int ni = 0; ni < 4; ni++) {
                    float2 v;
                    v.x = acc[mi][ni][rr * 2 + 0];
                    v.y = acc[mi][ni][rr * 2 + 1];
                    if (BIAS) {
                        const float* bp = bias + n0 + wn + (ni << 3) + ec;
                        v.x += bp[0]; v.y += bp[1];
                    }
                    if (ACC) {
                        float2 o = *reinterpret_cast<const float2*>(cp + (ni << 3));
                        v.x += o.x; v.y += o.y;
                    }
                    *reinterpret_cast<float2*>(cp + (ni << 3)) = v;
                }
            }
        }
    }
}

// ================= embed + reset (merged) =================
__global__ void embed_reset_k(const int* __restrict__ x, const float* __restrict__ tok) {
    int idx = blockIdx.x * blockDim.x + threadIdx.x;
    int stride = gridDim.x * blockDim.x;
    for (int i = idx; i < kS * 64; i += stride) g_flags[i] = 0;
    if (idx < kB * kD) { g_h[0][idx] = 0.f; g_h[1][idx] = 0.f; }
    for (int i = idx; i < kBS * (kD / 4); i += stride) {
        int bs = i / (kD / 4);
        int dq = i % (kD / 4);
        int tid = x[bs];
        float4 v = reinterpret_cast<const float4*>(tok + (size_t)tid * kD)[dq];
        __nv_bfloat162 a = __floats2bfloat162_rn(v.x, v.y);
        __nv_bfloat162 b = __floats2bfloat162_rn(v.z, v.w);
        uint2 u;
        u.x = *reinterpret_cast<uint32_t*>(&a);
        u.y = *reinterpret_cast<uint32_t*>(&b);
        *reinterpret_cast<uint2*>(bf_attn + (size_t)bs * kD2 + kD + dq * 4) = u;
    }
}

__global__ void conv_k(const float* __restrict__ in, __nv_bfloat16* __restrict__ out, int n4) {
    int i = blockIdx.x * blockDim.x + threadIdx.x;
    int stride = gridDim.x * blockDim.x;
    for (; i < n4; i += stride) {
        float4 v = reinterpret_cast<const float4*>(in)[i];
        __nv_bfloat162 a = __floats2bfloat162_rn(v.x, v.y);
        __nv_bfloat162 b = __floats2bfloat162_rn(v.z, v.w);
        uint2 u;
        u.x = *reinterpret_cast<uint32_t*>(&a);
        u.y = *reinterpret_cast<uint32_t*>(&b);
        reinterpret_cast<uint2*>(out)[i] = u;
    }
}

// bf_attn [b][j][e] -> bf_attnT [b][e][j]
__global__ void __launch_bounds__(256) convT_k() {
    __shared__ __nv_bfloat16 tile[32][33];
    int b  = blockIdx.z;
    int e0 = blockIdx.x * 32, j0 = blockIdx.y * 32;
    int tx = threadIdx.x & 31, ty = threadIdx.x >> 5;
#pragma unroll
    for (int i = 0; i < 32; i += 8)
        tile[ty + i][tx] = bf_attn[((size_t)b * kS + j0 + ty + i) * kD2 + e0 + tx];
    __syncthreads();
#pragma unroll
    for (int i = 0; i < 32; i += 8)
        bf_attnT[((size_t)b * kD2 + e0 + ty + i) * kS + j0 + tx] = tile[tx][ty + i];
}

// ---------------- persistent GRU scan (R10 protocol, unchanged) ----------------
__global__ void __launch_bounds__(256)
gru_k(const float* __restrict__ Whh, const float* __restrict__ bhh) {
    __shared__ float sh[kB * kD];
    const int w = threadIdx.x >> 5;
    const int l = threadIdx.x & 31;
    const int d = blockIdx.x * 8 + w;
    const int t = threadIdx.x;

    float Wr[16], Wz[16], Wn[16];
#pragma unroll
    for (int i = 0; i < 16; i++) {
        Wr[i] = Whh[(size_t)d * kD + l + 32 * i];
        Wz[i] = Whh[(size_t)(kD + d) * kD + l + 32 * i];
        Wn[i] = Whh[(size_t)(2 * kD + d) * kD + l + 32 * i];
    }
    const float bhr = bhh[d], bhz = bhh[kD + d], bhn = bhh[2 * kD + d];

    for (int s = 0; s < kS; s++) {
        const float* gx0 = g_gx + (size_t)s * kD3;
        const float* gx1 = g_gx + ((size_t)kS + s) * kD3;
        float gr0, gz0, gn0, gr1, gz1, gn1;
        if (l == 0) {
            gr0 = __ldg(gx0 + d);            gz0 = __ldg(gx0 + kD + d);
            gn0 = __ldg(gx0 + 2 * kD + d);   gr1 = __ldg(gx1 + d);
            gz1 = __ldg(gx1 + kD + d);       gn1 = __ldg(gx1 + 2 * kD + d);
        }

        const float* hb = g_h[s & 1];
#pragma unroll
        for (int i = 0; i < 4; i++) sh[t + (i << 8)] = __ldcv(hb + t + (i << 8));
        __syncthreads();

        float h0[16], h1[16];
#pragma unroll
        for (int i = 0; i < 16; i++) {
            h0[i] = sh[l + 32 * i];
            h1[i] = sh[kD + l + 32 * i];
        }
        float r0 = 0, z0 = 0, n0 = 0, r1 = 0, z1 = 0, n1 = 0;
#pragma unroll
        for (int i = 0; i < 16; i++) {
            r0 += h0[i] * Wr[i]; z0 += h0[i] * Wz[i]; n0 += h0[i] * Wn[i];
            r1 += h1[i] * Wr[i]; z1 += h1[i] * Wz[i]; n1 += h1[i] * Wn[i];
        }
#pragma unroll
        for (int o = 16; o > 0; o >>= 1) {
            r0 += __shfl_xor_sync(0xffffffffu, r0, o);
            z0 += __shfl_xor_sync(0xffffffffu, z0, o);
            n0 += __shfl_xor_sync(0xffffffffu, n0, o);
            r1 += __shfl_xor_sync(0xffffffffu, r1, o);
            z1 += __shfl_xor_sync(0xffffffffu, z1, o);
            n1 += __shfl_xor_sync(0xffffffffu, n1, o);
        }
        float hn0, hn1;
        if (l == 0) {
            float hp0 = sh[d];
            float hp1 = sh[kD + d];

            float r = 1.f / (1.f + __expf(-(gr0 + r0 + bhr)));
            float z = 1.f / (1.f + __expf(-(gz0 + z0 + bhz)));
            float n = tanhf(gn0 + r * (n0 + bhn));
            hn0 = (1.f - z) * n + z * hp0;

            r = 1.f / (1.f + __expf(-(gr1 + r1 + bhr)));
            z = 1.f / (1.f + __expf(-(gz1 + z1 + bhz)));
            n = tanhf(gn1 + r * (n1 + bhn));
            hn1 = (1.f - z) * n + z * hp1;

            float* hnext = g_h[(s + 1) & 1];
            hnext[d] = hn0;
            hnext[kD + d] = hn1;
        }
        __syncthreads();
        if (t == 0) {
            __threadfence();
            ((volatile int*)g_flags)[s * 64 + blockIdx.x] = 1;
        }
        if (l == 0) {
            bf_attn[(size_t)s * kD2 + d] = __float2bfloat16(hn0);
            bf_attn[((size_t)kS + s) * kD2 + d] = __float2bfloat16(hn1);
            bf_comb[(size_t)s * kD3 + d] = __float2bfloat16(hn0);
            bf_comb[((size_t)kS + s) * kD3 + d] = __float2bfloat16(hn1);
        }
        volatile int* vf = (volatile int*)(g_flags + s * 64);
        while (!__syncthreads_and(t < 64 ? (vf[t] != 0) : 1)) {}
        asm volatile("" ::: "memory");
    }
}

// ---------------- reductions (NW warps) ----------------
template <int NW>
__device__ __forceinline__ float bred_max(float v, volatile float* red) {
#pragma unroll
    for (int o = 16; o > 0; o >>= 1) v = fmaxf(v, __shfl_xor_sync(0xffffffffu, v, o));
    if ((threadIdx.x & 31) == 0) red[threadIdx.x >> 5] = v;
    __syncthreads();
    v = red[0];
#pragma unroll
    for (int k = 1; k < NW; k++) v = fmaxf(v, red[k]);
    __syncthreads();
    return v;
}
template <int NW>
__device__ __forceinline__ float bred_sum(float v, volatile float* red) {
#pragma unroll
    for (int o = 16; o > 0; o >>= 1) v += __shfl_xor_sync(0xffffffffu, v, o);
    if ((threadIdx.x & 31) == 0) red[threadIdx.x >> 5] = v;
    __syncthreads();
    v = red[0];
#pragma unroll
    for (int k = 1; k < NW; k++) v += red[k];
    __syncthreads();
    return v;
}

// ---------------- causal softmax: fp32 probs + bf16 probs ----------------
__global__ void __launch_bounds__(256) softmax_causal_k() {
    __shared__ float buf[kS];
    __shared__ float red[8];
    const int row = blockIdx.x;
    const int i   = row & (kS - 1);
    float* sr = g_sc + (size_t)row * kS;
    __nv_bfloat16* br = bf_probs + (size_t)row * kS;
    const float scale = 0.022097086912079612f;
    const int t = threadIdx.x;

    float mx = -1e30f;
    for (int j = t; j <= i; j += 256) {
        float v = sr[j] * scale;
        buf[j] = v;
        mx = fmaxf(mx, v);
    }
    mx = bred_max<8>(mx, red);
    float sum = 0.f;
    for (int j = t; j <= i; j += 256) {
        float e = fexp(buf[j] - mx);
        buf[j] = e;
        sum += e;
    }
    sum = bred_sum<8>(sum, red);
    float inv = 1.f / sum;
    for (int j = t; j < kS; j += 256) {
        float v = (j <= i) ? buf[j] * inv : 0.f;
        sr[j] = v;
        br[j] = __float2bfloat16(v);
    }
}

// ---------------- gate ----------------
__global__ void __launch_bounds__(256)
gate_k(const float* __restrict__ Wg, const float* __restrict__ bg) {
    int row = blockIdx.x * 8 + (threadIdx.x >> 5);
    int l = threadIdx.x & 31;
    const __nv_bfloat16* c = bf_comb + (size_t)row * kD3;
    float acc = 0.f;
    for (int k = l; k < kD3; k += 32) acc += __bfloat162float(c[k]) * Wg[k];
#pragma unroll
    for (int o = 16; o > 0; o >>= 1) acc += __shfl_xor_sync(0xffffffffu, acc, o);
    if (l == 0) g_gate[row] = 1.f / (1.f + expf(-(acc + bg[0])));
}

// ---------------- finalize (512 threads, FMA-pipe exp) ----------------
__global__ void __launch_bounds__(512)
finalize_k(const int* __restrict__ x, float* __restrict__ out) {
    extern __shared__ float row[];
    __shared__ float red[16];
    const int r = blockIdx.x;
    const int b = r >> 10;
    const int i = r & (kS - 1);
    float* orow = out + (size_t)r * kV;
    const int t = threadIdx.x;

    float4* orow4 = reinterpret_cast<float4*>(orow);
    float4* row4  = reinterpret_cast<float4*>(row);

    float mx = -1e30f;
    for (int j = t; j < kV / 4; j += 512) {
        float4 v = orow4[j];
        row4[j] = v;
        mx = fmaxf(mx, fmaxf(fmaxf(v.x, v.y), fmaxf(v.z, v.w)));
    }
    mx = bred_max<16>(mx, red);

    float sum = 0.f;
    for (int j = t; j < kV / 4; j += 512) {
        float4 v = row4[j];
        v.x = fexp(v.x - mx); v.y = fexp(v.y - mx);
        v.z = fexp(v.z - mx); v.w = fexp(v.w - mx);
        row4[j] = v;
        sum += v.x + v.y + v.z + v.w;
    }
    sum = bred_sum<16>(sum, red);

    const float g = g_gate[r];
    const float a = g / sum;
    for (int j = t; j < kV / 4; j += 512) {
        float4 v = row4[j];
        v.x *= a; v.y *= a; v.z *= a; v.w *= a;
        row4[j] = v;
    }
    __syncthreads();

    const float cg = 1.f - g;
    const float* pr = g_sc + (size_t)r * kS;
    const int* xb = x + b * kS;
    for (int j = t; j <= i; j += 512) {
        atomicAdd(&row[xb[j]], cg * pr[j]);
    }
    __syncthreads();
    for (int j = t; j < kV / 4; j += 512) orow4[j] = row4[j];
}

// ---------------- host driver ----------------
extern "C" void kernel_launch(void* const* d_in, const int* in_sizes, int n_in,
                              void* d_out, int out_size) {
    const int*   x     = (const int*)d_in[0];
    const float* tok   = (const float*)d_in[1];
    const float* pos   = (const float*)d_in[2];
    const float* W_ih  = (const float*)d_in[3];
    const float* W_hh  = (const float*)d_in[4];
    const float* b_ih  = (const float*)d_in[5];
    const float* b_hh  = (const float*)d_in[6];
    const float* Wq    = (const float*)d_in[7];
    const float* Wk    = (const float*)d_in[8];
    const float* Wqp   = (const float*)d_in[9];
    const float* Wgen  = (const float*)d_in[10];
    const float* bgen  = (const float*)d_in[11];
    const float* Wgate = (const float*)d_in[12];
    const float* bgate = (const float*)d_in[13];
    float* out = (float*)d_out;

    void* p;
    float *gx, *sc;
    __nv_bfloat16 *bAttn, *bWih, *bWq, *bWk, *bWqp, *bWgen, *bPos, *bQ, *bK, *bQp, *bProbs, *bAttnT, *bComb;
    cudaGetSymbolAddress(&p, g_gx);    gx    = (float*)p;
    cudaGetSymbolAddress(&p, g_sc);    sc    = (float*)p;
    cudaGetSymbolAddress(&p, bf_attn);  bAttn  = (__nv_bfloat16*)p;
    cudaGetSymbolAddress(&p, bf_Wih);   bWih   = (__nv_bfloat16*)p;
    cudaGetSymbolAddress(&p, bf_Wq);    bWq    = (__nv_bfloat16*)p;
    cudaGetSymbolAddress(&p, bf_Wk);    bWk    = (__nv_bfloat16*)p;
    cudaGetSymbolAddress(&p, bf_Wqp);   bWqp   = (__nv_bfloat16*)p;
    cudaGetSymbolAddress(&p, bf_Wgen);  bWgen  = (__nv_bfloat16*)p;
    cudaGetSymbolAddress(&p, bf_pos);   bPos   = (__nv_bfloat16*)p;
    cudaGetSymbolAddress(&p, bf_Q);     bQ     = (__nv_bfloat16*)p;
    cudaGetSymbolAddress(&p, bf_K);     bK     = (__nv_bfloat16*)p;
    cudaGetSymbolAddress(&p, bf_Qp);    bQp    = (__nv_bfloat16*)p;
    cudaGetSymbolAddress(&p, bf_probs); bProbs = (__nv_bfloat16*)p;
    cudaGetSymbolAddress(&p, bf_attnT); bAttnT = (__nv_bfloat16*)p;
    cudaGetSymbolAddress(&p, bf_comb);  bComb  = (__nv_bfloat16*)p;

    cudaFuncSetAttribute(finalize_k, cudaFuncAttributeMaxDynamicSharedMemorySize, kV * 4);
    cudaFuncSetAttribute(tgemm_k<false, true,  false, false, false>, cudaFuncAttributeMaxDynamicSharedMemorySize, TG_SMEM);
    cudaFuncSetAttribute(tgemm_k<false, false, false, true,  true>,  cudaFuncAttributeMaxDynamicSharedMemorySize, TG_SMEM);
    cudaFuncSetAttribute(tgemm_k<false, false, false, true,  false>, cudaFuncAttributeMaxDynamicSharedMemorySize, TG_SMEM);
    cudaFuncSetAttribute(tgemm_k<false, false, true,  false, false>, cudaFuncAttributeMaxDynamicSharedMemorySize, TG_SMEM);
    cudaFuncSetAttribute(tgemm_k<true,  false, true,  false, false>, cudaFuncAttributeMaxDynamicSharedMemorySize, TG_SMEM);

    embed_reset_k<<<1024, 256>>>(x, tok);                                       // 1
    conv_k<<<512, 256>>>(W_ih, bWih, kD3 * kD / 4);                             // 2
    tgemm_k<false, true, false, false, false><<<dim3(kD3 / 128, kBS / 128, 1), 256, TG_SMEM>>>(  // 3
        bAttn + kD, bWih, b_ih, gx, kD, kD2, kD, kD3, 0, 0, 0);
    gru_k<<<64, 256>>>(W_hh, b_hh);                                             // 4

    conv_k<<<4096, 256>>>(Wgen, bWgen, (int)((size_t)kV * kD3 / 4));
    conv_k<<<1024, 256>>>(Wq,   bWq,   kD2 * kD2 / 4);
    conv_k<<<1024, 256>>>(Wk,   bWk,   kD2 * kD2 / 4);
    conv_k<<<1024, 256>>>(Wqp,  bWqp,  kD * kD2 / 4);
    conv_k<<<512,  256>>>(pos,  bPos,  kS * kD / 4);

    // Q / K projections with fused RoPE (bf16 out); Qpos projection (bf16 out)
    tgemm_k<false, false, false, true, true><<<dim3(kD2 / 128, kBS / 128, 1), 256, TG_SMEM>>>(
        bAttn, bWq, nullptr, bQ, kD2, kD2, kD2, kD2, 0, 0, 0);
    tgemm_k<false, false, false, true, true><<<dim3(kD2 / 128, kBS / 128, 1), 256, TG_SMEM>>>(
        bAttn, bWk, nullptr, bK, kD2, kD2, kD2, kD2, 0, 0, 0);
    tgemm_k<false, false, false, true, false><<<dim3(kD / 128, kBS / 128, 1), 256, TG_SMEM>>>(
        bAttn, bWqp, nullptr, bQp, kD2, kD2, kD2, kD, 0, 0, 0);

    convT_k<<<dim3(kD2 / 32, kS / 32, kB), 256>>>();

    // scores = Q @ K^T, += Qpos @ pos^T (causal tiles skipped)
    tgemm_k<false, false, true, false, false><<<dim3(kS / 128, kS / 128, kB), 256, TG_SMEM>>>(
        bQ, bK, nullptr, sc, kD2, kD2, kD2, kS,
        (long long)kS * kD2, (long long)kS * kD2, (long long)kS * kS);
    tgemm_k<true, false, true, false, false><<<dim3(kS / 128, kS / 128, kB), 256, TG_SMEM>>>(
        bQp, bPos, nullptr, sc, kD, kD, kD, kS,
        (long long)kS * kD, 0, (long long)kS * kS);

    softmax_causal_k<<<kBS, 256>>>();

    // context = probs @ attn_in -> bf_comb[..., D:3D]
    tgemm_k<false, false, false, true, false><<<dim3(kD2 / 128, kS / 128, kB), 256, TG_SMEM>>>(
        bProbs, bAttnT, nullptr, bComb + kD, kS, kS, kS, kD3,
        (long long)kS * kS, (long long)kD2 * kS, (long long)kS * kD3);

    gate_k<<<kBS / 8, 256>>>(Wgate, bgate);

    // logits = combined @ Wgen^T + bgen
    tgemm_k<false, true, false, false, false><<<dim3(kV / 128, kBS / 128, 1), 256, TG_SMEM>>>(
        bComb, bWgen, bgen, out, kD3, kD3, kD3, kV, 0, 0, 0);

    finalize_k<<<kBS, 512, kV * 4>>>(x, out);
}

// round 16
// speedup vs baseline: 1.0125x; 1.0125x over previous
#include <cuda_runtime.h>
#include <cuda_bf16.h>
#include <cstdint>
#include <stdint.h>
#include <math.h>

namespace {
constexpr int kB  = 2;
constexpr int kS  = 1024;
constexpr int kD  = 512;
constexpr int kV  = 32000;
constexpr int kD2 = 2 * kD;   // 1024
constexpr int kD3 = 3 * kD;   // 1536
constexpr int kBS = kB * kS;  // 2048
}

// ---------------- fp32 scratch ----------------
__device__ float g_gx[kBS * kD3];
__device__ float g_sc[kBS * kS];
__device__ float g_h[2][kB * kD];
__device__ int   g_flags[kS * 64];
__device__ float g_gate[kBS];

// ---------------- bf16 scratch ----------------
__device__ __nv_bfloat16 bf_attn[kBS * kD2];
__device__ __nv_bfloat16 bf_Wih[kD3 * kD];
__device__ __nv_bfloat16 bf_Wq[kD2 * kD2];
__device__ __nv_bfloat16 bf_Wk[kD2 * kD2];
__device__ __nv_bfloat16 bf_Wqp[kD * kD2];
__device__ __nv_bfloat16 bf_Wgen[(size_t)kV * kD3];
__device__ __nv_bfloat16 bf_pos[kS * kD];
__device__ __nv_bfloat16 bf_Q[kBS * kD2];
__device__ __nv_bfloat16 bf_K[kBS * kD2];
__device__ __nv_bfloat16 bf_Qp[kBS * kD];
__device__ __nv_bfloat16 bf_probs[kBS * kS];
__device__ __nv_bfloat16 bf_attnT[kB * kD2 * kS];
__device__ __nv_bfloat16 bf_comb[kBS * kD3];

// ================= PTX helpers =================
__device__ __forceinline__ uint32_t smem_u32(const void* p) {
    uint32_t a;
    asm("{ .reg .u64 t; cvta.to.shared.u64 t, %1; cvt.u32.u64 %0, t; }" : "=r"(a) : "l"(p));
    return a;
}
__device__ __forceinline__ void cp16(uint32_t saddr, const void* gaddr) {
    asm volatile("cp.async.cg.shared.global [%0], [%1], 16;" :: "r"(saddr), "l"(gaddr));
}
#define CP_COMMIT() asm volatile("cp.async.commit_group;" ::: "memory")
#define CP_WAIT2()  asm volatile("cp.async.wait_group 2;" ::: "memory")

__device__ __forceinline__ void ldmat_x4(uint32_t& r0, uint32_t& r1, uint32_t& r2, uint32_t& r3,
                                         uint32_t addr) {
    asm volatile("ldmatrix.sync.aligned.m8n8.x4.shared.b16 {%0,%1,%2,%3}, [%4];"
                 : "=r"(r0), "=r"(r1), "=r"(r2), "=r"(r3) : "r"(addr));
}
__device__ __forceinline__ void mma_16816f(float* c, const uint32_t* a, const uint32_t* b) {
    asm volatile("mma.sync.aligned.m16n8k16.row.col.f32.bf16.bf16.f32 "
                 "{%0,%1,%2,%3}, {%4,%5,%6,%7}, {%8,%9}, {%0,%1,%2,%3};"
                 : "+f"(c[0]), "+f"(c[1]), "+f"(c[2]), "+f"(c[3])
                 : "r"(a[0]), "r"(a[1]), "r"(a[2]), "r"(a[3]), "r"(b[0]), "r"(b[1]));
}

// Fast exp on the FMA/ALU pipes (no MUFU). Rel err ~4e-5 for x <= 0.
__device__ __forceinline__ float fexp(float x) {
    x = fmaxf(x, -80.f);
    float y = x * 1.44269504088896f;
    float t = y + 12582912.f;
    float n = t - 12582912.f;
    float f = y - n;
    float p = 9.61597636e-3f;
    p = fmaf(p, f, 5.55036329e-2f);
    p = fmaf(p, f, 2.40226507e-1f);
    p = fmaf(p, f, 6.93147182e-1f);
    p = fmaf(p, f, 1.0f);
    int e = __float_as_int(t) << 23;
    return __int_as_float(__float_as_int(p) + e);
}

// ================= bf16 HMMA GEMM, cp.async 4-stage (R10 geometry, hoisted fragments) ========
// 256 threads = 8 warps (2x4), warp tile 64x32. CTA tile 128x128, K-chunk 32, 4 stages.
namespace {
constexpr int TS = 40;
constexpr uint32_t STAGE_BYTES = 256u * TS * 2;         // 20480
constexpr uint32_t TG_SMEM = 4 * STAGE_BYTES;           // 81920
constexpr float kRopeC = 0.017988946039015983f;         // ln(10000)/512
}

template <bool ACC, bool BIAS, bool CAUSAL, bool OUTBF, bool ROPE>
__global__ void __launch_bounds__(256)
tgemm_k(const __nv_bfloat16* __restrict__ A, const __nv_bfloat16* __restrict__ B,
        const float* __restrict__ bias, void* __restrict__ Cv,
        int K, int lda, int ldb, int ldc,
        long long sA, long long sB, long long sC) {
    const int m0 = blockIdx.y << 7;
    const int n0 = blockIdx.x << 7;
    if (CAUSAL && n0 > m0 + 127) return;
    A += (long long)blockIdx.z * sA;
    B += (long long)blockIdx.z * sB;

    extern __shared__ __nv_bfloat16 smem_bf[];
    const uint32_t sbase = smem_u32(smem_bf);

    const int t    = threadIdx.x;
    const int wid  = t >> 5;
    const int lane = t & 31;
    const int wm   = (wid >> 2) << 6;
    const int wn   = (wid & 3) << 5;

    const int rt = t >> 1;
    const int hf = (t & 1) << 4;

    const int a_r   = lane & 15;
    const int a_k   = (lane >> 4) << 3;
    const int b_row = (lane & 7) + ((lane >> 4) << 3);
    const int b_k   = ((lane >> 3) & 1) << 3;

    float acc[4][4][4];
#pragma unroll
    for (int i = 0; i < 4; i++)
#pragma unroll
        for (int j = 0; j < 4; j++)
#pragma unroll
            for (int r = 0; r < 4; r++) acc[i][j][r] = 0.f;

    auto stage_load = [&](int stage, int kb) {
        const __nv_bfloat16* ga = A + (size_t)(m0 + rt) * lda + (kb << 5) + hf;
        uint32_t sa = sbase + stage * STAGE_BYTES + ((uint32_t)(rt * TS + hf) << 1);
        cp16(sa, ga); cp16(sa + 16, ga + 8);
        const __nv_bfloat16* gb = B + (size_t)(n0 + rt) * ldb + (kb << 5) + hf;
        uint32_t sb = sbase + stage * STAGE_BYTES + ((uint32_t)((128 + rt) * TS + hf) << 1);
        cp16(sb, gb); cp16(sb + 16, gb + 8);
    };

    const int NKB = K >> 5;
    stage_load(0, 0);
    CP_COMMIT();
    if (NKB > 1) stage_load(1, 1);
    CP_COMMIT();
    if (NKB > 2) stage_load(2, 2);
    CP_COMMIT();

    int buf = 0;
    for (int kb = 0; kb < NKB; kb++) {
        CP_WAIT2();
        __syncthreads();

        const uint32_t ab = sbase + buf * STAGE_BYTES;
        const uint32_t bb = ab + 128u * TS * 2;

        // hoist all fragments for the full 32-wide chunk, then issue all MMAs
        uint32_t af[2][4][4], bfr[2][4][2];
#pragma unroll
        for (int h = 0; h < 2; h++) {
            const int ks = h << 4;
#pragma unroll
            for (int mi = 0; mi < 4; mi++) {
                uint32_t addr = ab + ((uint32_t)((wm + (mi << 4) + a_r) * TS + ks + a_k) << 1);
                ldmat_x4(af[h][mi][0], af[h][mi][1], af[h][mi][2], af[h][mi][3], addr);
            }
#pragma unroll
            for (int np = 0; np < 2; np++) {
                uint32_t addr = bb + ((uint32_t)((wn + (np << 4) + b_row) * TS + ks + b_k) << 1);
                ldmat_x4(bfr[h][np * 2][0], bfr[h][np * 2][1],
                         bfr[h][np * 2 + 1][0], bfr[h][np * 2 + 1][1], addr);
            }
        }
#pragma unroll
        for (int h = 0; h < 2; h++)
#pragma unroll
            for (int mi = 0; mi < 4; mi++)
#pragma unroll
                for (int ni = 0; ni < 4; ni++)
                    mma_16816f(acc[mi][ni], af[h][mi], bfr[h][ni]);

        if (kb + 3 < NKB) {
            int ns = buf + 3; if (ns >= 4) ns -= 4;
            stage_load(ns, kb + 3);
        }
        CP_COMMIT();
        if (++buf == 4) buf = 0;
    }

    // epilogue
    const int er = lane >> 2;
    const int ec = (lane & 3) << 1;
    if (OUTBF) {
        __nv_bfloat16* Cb = (__nv_bfloat16*)Cv + (long long)blockIdx.z * sC;
#pragma unroll
        for (int mi = 0; mi < 4; mi++) {
#pragma unroll
            for (int rr = 0; rr < 2; rr++) {
                int m = m0 + wm + (mi << 4) + er + (rr << 3);
                __nv_bfloat16* cp = Cb + (size_t)m * ldc + n0 + wn + ec;
                float sp = ROPE ? (float)(m & (kS - 1)) : 0.f;
#pragma unroll
                for (int ni = 0; ni < 4; ni++) {
                    float vx = acc[mi][ni][rr * 2 + 0];
                    float vy = acc[mi][ni][rr * 2 + 1];
                    if (ROPE) {
                        int col = n0 + wn + (ni << 3) + ec;
                        float inv = expf(-kRopeC * (float)(col >> 1));
                        float sn, cs;
                        sincosf(sp * inv, &sn, &cs);
                        float rx = vx * cs - vy * sn;
                        float ry = vy * cs + vx * sn;
                        vx = rx; vy = ry;
                    }
                    __nv_bfloat162 h = __floats2bfloat162_rn(vx, vy);
                    *reinterpret_cast<__nv_bfloat162*>(cp + (ni << 3)) = h;
                }
            }
        }
    } else {
        float* Cf = (float*)Cv + (long long)blockIdx.z * sC;
#pragma unroll
        for (int mi = 0; mi < 4; mi++) {
#pragma unroll
            for (int rr = 0; rr < 2; rr++) {
                int m = m0 + wm + (mi << 4) + er + (rr << 3);
                float* cp = Cf + (size_t)m * ldc + n0 + wn + ec;
#pragma unroll
                for (int ni = 0; ni < 4; ni++) {
                    float2 v;
                    v.x = acc[mi][ni][rr * 2 + 0];
                    v.y = acc[mi][ni][rr * 2 + 1];
                    if (BIAS) {
                        const float* bp = bias + n0 + wn + (ni << 3) + ec;
                        v.x += bp[0]; v.y += bp[1];
                    }
                    if (ACC) {
                        float2 o = *reinterpret_cast<const float2*>(cp + (ni << 3));
                        v.x += o.x; v.y += o.y;
                    }
                    *reinterpret_cast<float2*>(cp + (ni << 3)) = v;
                }
            }
        }
    }
}

// ================= embed + reset (merged) =================
__global__ void embed_reset_k(const int* __restrict__ x, const float* __restrict__ tok) {
    int idx = blockIdx.x * blockDim.x + threadIdx.x;
    int stride = gridDim.x * blockDim.x;
    for (int i = idx; i < kS * 64; i += stride) g_flags[i] = 0;
    if (idx < kB * kD) { g_h[0][idx] = 0.f; g_h[1][idx] = 0.f; }
    for (int i = idx; i < kBS * (kD / 4); i += stride) {
        int bs = i / (kD / 4);
        int dq = i % (kD / 4);
        int tid = x[bs];
        float4 v = reinterpret_cast<const float4*>(tok + (size_t)tid * kD)[dq];
        __nv_bfloat162 a = __floats2bfloat162_rn(v.x, v.y);
        __nv_bfloat162 b = __floats2bfloat162_rn(v.z, v.w);
        uint2 u;
        u.x = *reinterpret_cast<uint32_t*>(&a);
        u.y = *reinterpret_cast<uint32_t*>(&b);
        *reinterpret_cast<uint2*>(bf_attn + (size_t)bs * kD2 + kD + dq * 4) = u;
    }
}

__global__ void conv_k(const float* __restrict__ in, __nv_bfloat16* __restrict__ out, int n4) {
    int i = blockIdx.x * blockDim.x + threadIdx.x;
    int stride = gridDim.x * blockDim.x;
    for (; i < n4; i += stride) {
        float4 v = reinterpret_cast<const float4*>(in)[i];
        __nv_bfloat162 a = __floats2bfloat162_rn(v.x, v.y);
        __nv_bfloat162 b = __floats2bfloat162_rn(v.z, v.w);
        uint2 u;
        u.x = *reinterpret_cast<uint32_t*>(&a);
        u.y = *reinterpret_cast<uint32_t*>(&b);
        reinterpret_cast<uint2*>(out)[i] = u;
    }
}

// bf_attn [b][j][e] -> bf_attnT [b][e][j]
__global__ void __launch_bounds__(256) convT_k() {
    __shared__ __nv_bfloat16 tile[32][33];
    int b  = blockIdx.z;
    int e0 = blockIdx.x * 32, j0 = blockIdx.y * 32;
    int tx = threadIdx.x & 31, ty = threadIdx.x >> 5;
#pragma unroll
    for (int i = 0; i < 32; i += 8)
        tile[ty + i][tx] = bf_attn[((size_t)b * kS + j0 + ty + i) * kD2 + e0 + tx];
    __syncthreads();
#pragma unroll
    for (int i = 0; i < 32; i += 8)
        bf_attnT[((size_t)b * kD2 + e0 + ty + i) * kS + j0 + tx] = tile[tx][ty + i];
}

// ---------------- persistent GRU scan (R13 flag protocol, known good) ----------------
__global__ void __launch_bounds__(256)
gru_k(const float* __restrict__ Whh, const float* __restrict__ bhh) {
    __shared__ float sh[kB * kD];
    const int w = threadIdx.x >> 5;
    const int l = threadIdx.x & 31;
    const int d = blockIdx.x * 8 + w;
    const int t = threadIdx.x;

    float Wr[16], Wz[16], Wn[16];
#pragma unroll
    for (int i = 0; i < 16; i++) {
        Wr[i] = Whh[(size_t)d * kD + l + 32 * i];
        Wz[i] = Whh[(size_t)(kD + d) * kD + l + 32 * i];
        Wn[i] = Whh[(size_t)(2 * kD + d) * kD + l + 32 * i];
    }
    const float bhr = bhh[d], bhz = bhh[kD + d], bhn = bhh[2 * kD + d];

    for (int s = 0; s < kS; s++) {
        const float* gx0 = g_gx + (size_t)s * kD3;
        const float* gx1 = g_gx + ((size_t)kS + s) * kD3;
        float gr0, gz0, gn0, gr1, gz1, gn1;
        if (l == 0) {
            gr0 = __ldg(gx0 + d);            gz0 = __ldg(gx0 + kD + d);
            gn0 = __ldg(gx0 + 2 * kD + d);   gr1 = __ldg(gx1 + d);
            gz1 = __ldg(gx1 + kD + d);       gn1 = __ldg(gx1 + 2 * kD + d);
        }

        const float* hb = g_h[s & 1];
#pragma unroll
        for (int i = 0; i < 4; i++) sh[t + (i << 8)] = __ldcv(hb + t + (i << 8));
        __syncthreads();

        float h0[16], h1[16];
#pragma unroll
        for (int i = 0; i < 16; i++) {
            h0[i] = sh[l + 32 * i];
            h1[i] = sh[kD + l + 32 * i];
        }
        float r0 = 0, z0 = 0, n0 = 0, r1 = 0, z1 = 0, n1 = 0;
#pragma unroll
        for (int i = 0; i < 16; i++) {
            r0 += h0[i] * Wr[i]; z0 += h0[i] * Wz[i]; n0 += h0[i] * Wn[i];
            r1 += h1[i] * Wr[i]; z1 += h1[i] * Wz[i]; n1 += h1[i] * Wn[i];
        }
#pragma unroll
        for (int o = 16; o > 0; o >>= 1) {
            r0 += __shfl_xor_sync(0xffffffffu, r0, o);
            z0 += __shfl_xor_sync(0xffffffffu, z0, o);
            n0 += __shfl_xor_sync(0xffffffffu, n0, o);
            r1 += __shfl_xor_sync(0xffffffffu, r1, o);
            z1 += __shfl_xor_sync(0xffffffffu, z1, o);
            n1 += __shfl_xor_sync(0xffffffffu, n1, o);
        }
        float hn0, hn1;
        if (l == 0) {
            float hp0 = sh[d];
            float hp1 = sh[kD + d];

            float r = 1.f / (1.f + __expf(-(gr0 + r0 + bhr)));
            float z = 1.f / (1.f + __expf(-(gz0 + z0 + bhz)));
            float n = tanhf(gn0 + r * (n0 + bhn));
            hn0 = (1.f - z) * n + z * hp0;

            r = 1.f / (1.f + __expf(-(gr1 + r1 + bhr)));
            z = 1.f / (1.f + __expf(-(gz1 + z1 + bhz)));
            n = tanhf(gn1 + r * (n1 + bhn));
            hn1 = (1.f - z) * n + z * hp1;

            float* hnext = g_h[(s + 1) & 1];
            hnext[d] = hn0;
            hnext[kD + d] = hn1;
        }
        __syncthreads();
        if (t == 0) {
            __threadfence();
            ((volatile int*)g_flags)[s * 64 + blockIdx.x] = 1;
        }
        if (l == 0) {
            bf_attn[(size_t)s * kD2 + d] = __float2bfloat16(hn0);
            bf_attn[((size_t)kS + s) * kD2 + d] = __float2bfloat16(hn1);
            bf_comb[(size_t)s * kD3 + d] = __float2bfloat16(hn0);
            bf_comb[((size_t)kS + s) * kD3 + d] = __float2bfloat16(hn1);
        }
        volatile int* vf = (volatile int*)(g_flags + s * 64);
        while (!__syncthreads_and(t < 64 ? (vf[t] != 0) : 1)) {}
        asm volatile("" ::: "memory");
    }
}

// ---------------- reductions (NW warps) ----------------
template <int NW>
__device__ __forceinline__ float bred_max(float v, volatile float* red) {
#pragma unroll
    for (int o = 16; o > 0; o >>= 1) v = fmaxf(v, __shfl_xor_sync(0xffffffffu, v, o));
    if ((threadIdx.x & 31) == 0) red[threadIdx.x >> 5] = v;
    __syncthreads();
    v = red[0];
#pragma unroll
    for (int k = 1; k < NW; k++) v = fmaxf(v, red[k]);
    __syncthreads();
    return v;
}
template <int NW>
__device__ __forceinline__ float bred_sum(float v, volatile float* red) {
#pragma unroll
    for (int o = 16; o > 0; o >>= 1) v += __shfl_xor_sync(0xffffffffu, v, o);
    if ((threadIdx.x & 31) == 0) red[threadIdx.x >> 5] = v;
    __syncthreads();
    v = red[0];
#pragma unroll
    for (int k = 1; k < NW; k++) v += red[k];
    __syncthreads();
    return v;
}

// ---------------- causal softmax: fp32 probs + bf16 probs ----------------
__global__ void __launch_bounds__(256) softmax_causal_k() {
    __shared__ float buf[kS];
    __shared__ float red[8];
    const int row = blockIdx.x;
    const int i   = row & (kS - 1);
    float* sr = g_sc + (size_t)row * kS;
    __nv_bfloat16* br = bf_probs + (size_t)row * kS;
    const float scale = 0.022097086912079612f;
    const int t = threadIdx.x;

    float mx = -1e30f;
    for (int j = t; j <= i; j += 256) {
        float v = sr[j] * scale;
        buf[j] = v;
        mx = fmaxf(mx, v);
    }
    mx = bred_max<8>(mx, red);
    float sum = 0.f;
    for (int j = t; j <= i; j += 256) {
        float e = fexp(buf[j] - mx);
        buf[j] = e;
        sum += e;
    }
    sum = bred_sum<8>(sum, red);
    float inv = 1.f / sum;
    for (int j = t; j < kS; j += 256) {
        float v = (j <= i) ? buf[j] * inv : 0.f;
        sr[j] = v;
        br[j] = __float2bfloat16(v);
    }
}

// ---------------- gate ----------------
__global__ void __launch_bounds__(256)
gate_k(const float* __restrict__ Wg, const float* __restrict__ bg) {
    int row = blockIdx.x * 8 + (threadIdx.x >> 5);
    int l = threadIdx.x & 31;
    const __nv_bfloat16* c = bf_comb + (size_t)row * kD3;
    float acc = 0.f;
    for (int k = l; k < kD3; k += 32) acc += __bfloat162float(c[k]) * Wg[k];
#pragma unroll
    for (int o = 16; o > 0; o >>= 1) acc += __shfl_xor_sync(0xffffffffu, acc, o);
    if (l == 0) g_gate[row] = 1.f / (1.f + expf(-(acc + bg[0])));
}

// ---------------- finalize (512 threads, FMA-pipe exp) ----------------
__global__ void __launch_bounds__(512)
finalize_k(const int* __restrict__ x, float* __restrict__ out) {
    extern __shared__ float row[];
    __shared__ float red[16];
    const int r = blockIdx.x;
    const int b = r >> 10;
    const int i = r & (kS - 1);
    float* orow = out + (size_t)r * kV;
    const int t = threadIdx.x;

    float4* orow4 = reinterpret_cast<float4*>(orow);
    float4* row4  = reinterpret_cast<float4*>(row);

    float mx = -1e30f;
    for (int j = t; j < kV / 4; j += 512) {
        float4 v = orow4[j];
        row4[j] = v;
        mx = fmaxf(mx, fmaxf(fmaxf(v.x, v.y), fmaxf(v.z, v.w)));
    }
    mx = bred_max<16>(mx, red);

    float sum = 0.f;
    for (int j = t; j < kV / 4; j += 512) {
        float4 v = row4[j];
        v.x = fexp(v.x - mx); v.y = fexp(v.y - mx);
        v.z = fexp(v.z - mx); v.w = fexp(v.w - mx);
        row4[j] = v;
        sum += v.x + v.y + v.z + v.w;
    }
    sum = bred_sum<16>(sum, red);

    const float g = g_gate[r];
    const float a = g / sum;
    for (int j = t; j < kV / 4; j += 512) {
        float4 v = row4[j];
        v.x *= a; v.y *= a; v.z *= a; v.w *= a;
        row4[j] = v;
    }
    __syncthreads();

    const float cg = 1.f - g;
    const float* pr = g_sc + (size_t)r * kS;
    const int* xb = x + b * kS;
    for (int j = t; j <= i; j += 512) {
        atomicAdd(&row[xb[j]], cg * pr[j]);
    }
    __syncthreads();
    for (int j = t; j < kV / 4; j += 512) orow4[j] = row4[j];
}

// ---------------- host driver ----------------
extern "C" void kernel_launch(void* const* d_in, const int* in_sizes, int n_in,
                              void* d_out, int out_size) {
    const int*   x     = (const int*)d_in[0];
    const float* tok   = (const float*)d_in[1];
    const float* pos   = (const float*)d_in[2];
    const float* W_ih  = (const float*)d_in[3];
    const float* W_hh  = (const float*)d_in[4];
    const float* b_ih  = (const float*)d_in[5];
    const float* b_hh  = (const float*)d_in[6];
    const float* Wq    = (const float*)d_in[7];
    const float* Wk    = (const float*)d_in[8];
    const float* Wqp   = (const float*)d_in[9];
    const float* Wgen  = (const float*)d_in[10];
    const float* bgen  = (const float*)d_in[11];
    const float* Wgate = (const float*)d_in[12];
    const float* bgate = (const float*)d_in[13];
    float* out = (float*)d_out;

    void* p;
    float *gx, *sc;
    __nv_bfloat16 *bAttn, *bWih, *bWq, *bWk, *bWqp, *bWgen, *bPos, *bQ, *bK, *bQp, *bProbs, *bAttnT, *bComb;
    cudaGetSymbolAddress(&p, g_gx);    gx    = (float*)p;
    cudaGetSymbolAddress(&p, g_sc);    sc    = (float*)p;
    cudaGetSymbolAddress(&p, bf_attn);  bAttn  = (__nv_bfloat16*)p;
    cudaGetSymbolAddress(&p, bf_Wih);   bWih   = (__nv_bfloat16*)p;
    cudaGetSymbolAddress(&p, bf_Wq);    bWq    = (__nv_bfloat16*)p;
    cudaGetSymbolAddress(&p, bf_Wk);    bWk    = (__nv_bfloat16*)p;
    cudaGetSymbolAddress(&p, bf_Wqp);   bWqp   = (__nv_bfloat16*)p;
    cudaGetSymbolAddress(&p, bf_Wgen);  bWgen  = (__nv_bfloat16*)p;
    cudaGetSymbolAddress(&p, bf_pos);   bPos   = (__nv_bfloat16*)p;
    cudaGetSymbolAddress(&p, bf_Q);     bQ     = (__nv_bfloat16*)p;
    cudaGetSymbolAddress(&p, bf_K);     bK     = (__nv_bfloat16*)p;
    cudaGetSymbolAddress(&p, bf_Qp);    bQp    = (__nv_bfloat16*)p;
    cudaGetSymbolAddress(&p, bf_probs); bProbs = (__nv_bfloat16*)p;
    cudaGetSymbolAddress(&p, bf_attnT); bAttnT = (__nv_bfloat16*)p;
    cudaGetSymbolAddress(&p, bf_comb);  bComb  = (__nv_bfloat16*)p;

    cudaFuncSetAttribute(finalize_k, cudaFuncAttributeMaxDynamicSharedMemorySize, kV * 4);
    cudaFuncSetAttribute(tgemm_k<false, true,  false, false, false>, cudaFuncAttributeMaxDynamicSharedMemorySize, TG_SMEM);
    cudaFuncSetAttribute(tgemm_k<false, false, false, true,  true>,  cudaFuncAttributeMaxDynamicSharedMemorySize, TG_SMEM);
    cudaFuncSetAttribute(tgemm_k<false, false, false, true,  false>, cudaFuncAttributeMaxDynamicSharedMemorySize, TG_SMEM);
    cudaFuncSetAttribute(tgemm_k<false, false, true,  false, false>, cudaFuncAttributeMaxDynamicSharedMemorySize, TG_SMEM);
    cudaFuncSetAttribute(tgemm_k<true,  false, true,  false, false>, cudaFuncAttributeMaxDynamicSharedMemorySize, TG_SMEM);

    embed_reset_k<<<1024, 256>>>(x, tok);                                       // 1
    conv_k<<<512, 256>>>(W_ih, bWih, kD3 * kD / 4);                             // 2
    tgemm_k<false, true, false, false, false><<<dim3(kD3 / 128, kBS / 128, 1), 256, TG_SMEM>>>(  // 3
        bAttn + kD, bWih, b_ih, gx, kD, kD2, kD, kD3, 0, 0, 0);
    gru_k<<<64, 256>>>(W_hh, b_hh);                                             // 4

    conv_k<<<4096, 256>>>(Wgen, bWgen, (int)((size_t)kV * kD3 / 4));
    conv_k<<<1024, 256>>>(Wq,   bWq,   kD2 * kD2 / 4);
    conv_k<<<1024, 256>>>(Wk,   bWk,   kD2 * kD2 / 4);
    conv_k<<<1024, 256>>>(Wqp,  bWqp,  kD * kD2 / 4);
    conv_k<<<512,  256>>>(pos,  bPos,  kS * kD / 4);

    // Q / K projections with fused RoPE (bf16 out); Qpos projection (bf16 out)
    tgemm_k<false, false, false, true, true><<<dim3(kD2 / 128, kBS / 128, 1), 256, TG_SMEM>>>(
        bAttn, bWq, nullptr, bQ, kD2, kD2, kD2, kD2, 0, 0, 0);
    tgemm_k<false, false, false, true, true><<<dim3(kD2 / 128, kBS / 128, 1), 256, TG_SMEM>>>(
        bAttn, bWk, nullptr, bK, kD2, kD2, kD2, kD2, 0, 0, 0);
    tgemm_k<false, false, false, true, false><<<dim3(kD / 128, kBS / 128, 1), 256, TG_SMEM>>>(
        bAttn, bWqp, nullptr, bQp, kD2, kD2, kD2, kD, 0, 0, 0);

    convT_k<<<dim3(kD2 / 32, kS / 32, kB), 256>>>();

    // scores = Q @ K^T, += Qpos @ pos^T (causal tiles skipped)
    tgemm_k<false, false, true, false, false><<<dim3(kS / 128, kS / 128, kB), 256, TG_SMEM>>>(
        bQ, bK, nullptr, sc, kD2, kD2, kD2, kS,
        (long long)kS * kD2, (long long)kS * kD2, (long long)kS * kS);
    tgemm_k<true, false, true, false, false><<<dim3(kS / 128, kS / 128, kB), 256, TG_SMEM>>>(
        bQp, bPos, nullptr, sc, kD, kD, kD, kS,
        (long long)kS * kD, 0, (long long)kS * kS);

    softmax_causal_k<<<kBS, 256>>>();

    // context = probs @ attn_in -> bf_comb[..., D:3D]
    tgemm_k<false, false, false, true, false><<<dim3(kD2 / 128, kS / 128, kB), 256, TG_SMEM>>>(
        bProbs, bAttnT, nullptr, bComb + kD, kS, kS, kS, kD3,
        (long long)kS * kS, (long long)kD2 * kS, (long long)kS * kD3);

    gate_k<<<kBS / 8, 256>>>(Wgate, bgate);

    // logits = combined @ Wgen^T + bgen
    tgemm_k<false, true, false, false, false><<<dim3(kV / 128, kBS / 128, 1), 256, TG_SMEM>>>(
        bComb, bWgen, bgen, out, kD3, kD3, kD3, kV, 0, 0, 0);

    finalize_k<<<kBS, 512, kV * 4>>>(x, out);
}